// round 3
// baseline (speedup 1.0000x reference)
#include <cuda_runtime.h>

#define THREADS        128
#define WARPS          4
#define ROWS_PER_WARP  8
#define ROWS_PER_BLOCK 32          // WARPS * ROWS_PER_WARP
#define DIN            4096
#define DOUT           4096
#define RNK            16
#define KT             512         // A k-tile staged in smem
#define P2F            1028        // float pitch of one rank-pair row (KT*2+4), %32==4
#define NBATCH         (DIN / 16)  // 256 batches of 16 k
#define TBATCH         (KT / 16)   // 32 batches per A tile
#define NBLOCKS        256         // 8192 rows / 32

__device__ __forceinline__ unsigned long long pk2(float v) {
    unsigned long long r;
    asm("mov.b64 %0, {%1, %1};" : "=l"(r) : "f"(v));
    return r;
}
__device__ __forceinline__ void ffma2(unsigned long long &acc,
                                      unsigned long long a, unsigned long long b) {
    asm("fma.rn.f32x2 %0, %1, %2, %0;" : "+l"(acc) : "l"(a), "l"(b));
}
__device__ __forceinline__ unsigned long long add2(unsigned long long a,
                                                   unsigned long long b) {
    unsigned long long d;
    asm("add.rn.f32x2 %0, %1, %2;" : "=l"(d) : "l"(a), "l"(b));
    return d;
}

__global__ void __launch_bounds__(THREADS, 4)
lora_fused_kernel(const float* __restrict__ x,
                  const float* __restrict__ A,
                  const float* __restrict__ B,
                  float* __restrict__ out)
{
    // A tile, rank-pair major: As2[rp][k] holds A[k][2rp:2rp+1] (float2),
    // row pitch P2F floats (conflict-free for the quad access pattern).
    __shared__ float As2[8 * P2F];                          // ~33 KB
    __shared__ unsigned long long ts2[ROWS_PER_BLOCK][8];   // t as 8 rank-pairs

    const int tid  = threadIdx.x;
    const int lane = tid & 31;
    const int warp = tid >> 5;
    const int rp   = lane >> 2;          // rank-pair 0..7  (ranks 2rp, 2rp+1)
    const int ksub = lane & 3;           // k-quarter within a 16-k batch
    const long long rowBase  = (long long)blockIdx.x * ROWS_PER_BLOCK;
    const int       warpRow0 = warp * ROWS_PER_WARP;

    // ---------------- Phase 1: t[32,16] = x_rows @ A ----------------
    unsigned long long acc[ROWS_PER_WARP];   // 8 rows x 1 rank-pair = 16 regs
    #pragma unroll
    for (int r = 0; r < ROWS_PER_WARP; r++) acc[r] = 0ULL;

    const float* xw = x + (rowBase + warpRow0) * (long long)DIN + 4 * ksub;

    // preload x for batch 0
    float4 xv[ROWS_PER_WARP];
    #pragma unroll
    for (int r = 0; r < ROWS_PER_WARP; r++)
        xv[r] = *reinterpret_cast<const float4*>(&xw[(long long)r * DIN]);

    #pragma unroll 1
    for (int bb = 0; bb < NBATCH; bb++) {
        // reload A tile every TBATCH batches
        if ((bb & (TBATCH - 1)) == 0) {
            __syncthreads();
            const int t0 = bb * 16;
            const float2* Ag = reinterpret_cast<const float2*>(A) + (long long)t0 * 8;
            #pragma unroll
            for (int m = 0; m < (KT * 8) / THREADS; m++) {
                int i = tid + m * THREADS;          // f2 index: k = i/8, rp = i%8
                int k = i >> 3, r8 = i & 7;
                *reinterpret_cast<float2*>(&As2[r8 * P2F + 2 * k]) = Ag[i];
            }
            __syncthreads();
        }

        // LDS A fragment for this batch: 4 float2 (k = kb+4ksub .. +3)
        const int kin = (bb & (TBATCH - 1)) * 16 + 4 * ksub;   // k within tile
        const float* ap = &As2[rp * P2F + 2 * kin];
        ulonglong2 f0 = *reinterpret_cast<const ulonglong2*>(ap);
        ulonglong2 f1 = *reinterpret_cast<const ulonglong2*>(ap + 4);

        // prefetch x for next batch (independent of A tile)
        float4 xn[ROWS_PER_WARP];
        if (bb + 1 < NBATCH) {
            const float* xnp = xw + (bb + 1) * 16;
            #pragma unroll
            for (int r = 0; r < ROWS_PER_WARP; r++)
                xn[r] = *reinterpret_cast<const float4*>(&xnp[(long long)r * DIN]);
        }

        #pragma unroll
        for (int r = 0; r < ROWS_PER_WARP; r++) {
            ffma2(acc[r], pk2(xv[r].x), f0.x);
            ffma2(acc[r], pk2(xv[r].y), f0.y);
            ffma2(acc[r], pk2(xv[r].z), f1.x);
            ffma2(acc[r], pk2(xv[r].w), f1.y);
        }

        #pragma unroll
        for (int r = 0; r < ROWS_PER_WARP; r++) xv[r] = xn[r];
    }

    // reduce over the 4 k-quarters within each quad
    #pragma unroll
    for (int r = 0; r < ROWS_PER_WARP; r++) {
        acc[r] = add2(acc[r], __shfl_xor_sync(0xffffffffu, acc[r], 1));
        acc[r] = add2(acc[r], __shfl_xor_sync(0xffffffffu, acc[r], 2));
    }
    if (ksub == 0) {
        #pragma unroll
        for (int r = 0; r < ROWS_PER_WARP; r++)
            ts2[warpRow0 + r][rp] = acc[r];
    }
    __syncthreads();

    // ---------------- Phase 2: out[32,4096] = t @ B ----------------
    // 8 column passes of 512; thread owns 4 output columns, B cached in regs,
    // reused across all 32 rows. t read via broadcast LDS.
    #pragma unroll 1
    for (int p = 0; p < 8; p++) {
        const int j = p * 512 + tid * 4;
        ulonglong2 Breg[RNK];
        #pragma unroll
        for (int r = 0; r < RNK; r++)
            Breg[r] = *reinterpret_cast<const ulonglong2*>(B + (long long)r * DOUT + j);

        #pragma unroll 2
        for (int row = 0; row < ROWS_PER_BLOCK; row++) {
            const ulonglong2* tr = reinterpret_cast<const ulonglong2*>(ts2[row]);
            ulonglong2 t0 = tr[0], t1 = tr[1], t2 = tr[2], t3 = tr[3];
            float tv[RNK];
            *reinterpret_cast<ulonglong2*>(&tv[0])  = t0;
            *reinterpret_cast<ulonglong2*>(&tv[4])  = t1;
            *reinterpret_cast<ulonglong2*>(&tv[8])  = t2;
            *reinterpret_cast<ulonglong2*>(&tv[12]) = t3;

            unsigned long long accLo = 0ULL, accHi = 0ULL;
            #pragma unroll
            for (int r = 0; r < RNK; r++) {
                unsigned long long tp = pk2(tv[r]);
                ffma2(accLo, tp, Breg[r].x);
                ffma2(accHi, tp, Breg[r].y);
            }
            ulonglong2 o; o.x = accLo; o.y = accHi;
            *reinterpret_cast<ulonglong2*>(
                out + (rowBase + row) * (long long)DOUT + j) = o;
        }
    }
}

extern "C" void kernel_launch(void* const* d_in, const int* in_sizes, int n_in,
                              void* d_out, int out_size) {
    const float* x = (const float*)d_in[0];   // [4, 2048, 4096]
    const float* A = (const float*)d_in[1];   // [4096, 16]
    const float* B = (const float*)d_in[2];   // [16, 4096]
    float* out = (float*)d_out;               // [4, 2048, 4096]
    lora_fused_kernel<<<NBLOCKS, THREADS>>>(x, A, B, out);
}

// round 4
// speedup vs baseline: 2.4533x; 2.4533x over previous
#include <cuda_runtime.h>

#define THREADS        128
#define WARPS          4
#define ROWS_PER_WARP  8
#define ROWS_PER_BLOCK 32          // WARPS * ROWS_PER_WARP
#define DIN            4096
#define DOUT           4096
#define RNK            16
#define KT             128         // k per pipeline tile
#define NSTAGES        4
#define NTILES         (DIN / KT)  // 32
#define AP             260         // A rank-pair row pitch in floats (== 4 mod 32)
#define XS_F           (ROWS_PER_BLOCK * KT)   // 4096 floats / stage
#define AS_F           (8 * AP)                // 2080 floats / stage
#define STAGE_F        (XS_F + AS_F)           // 6176 floats
#define SMEM_BYTES     (NSTAGES * STAGE_F * 4) // 98816 B
#define NBLOCKS        256

__device__ __forceinline__ unsigned long long pk2(float v) {
    unsigned long long r;
    asm("mov.b64 %0, {%1, %1};" : "=l"(r) : "f"(v));
    return r;
}
__device__ __forceinline__ void ffma2(unsigned long long &acc,
                                      unsigned long long a, unsigned long long b) {
    asm("fma.rn.f32x2 %0, %1, %2, %0;" : "+l"(acc) : "l"(a), "l"(b));
}
__device__ __forceinline__ unsigned long long add2(unsigned long long a,
                                                   unsigned long long b) {
    unsigned long long d;
    asm("add.rn.f32x2 %0, %1, %2;" : "=l"(d) : "l"(a), "l"(b));
    return d;
}
__device__ __forceinline__ unsigned su32(const void* p) {
    unsigned a;
    asm("{ .reg .u64 t; cvta.to.shared.u64 t, %1; cvt.u32.u64 %0, t; }"
        : "=r"(a) : "l"(p));
    return a;
}
__device__ __forceinline__ void cpa16(unsigned d, const void* s) {
    asm volatile("cp.async.cg.shared.global [%0], [%1], 16;" :: "r"(d), "l"(s));
}
__device__ __forceinline__ void cpa8(unsigned d, const void* s) {
    asm volatile("cp.async.ca.shared.global [%0], [%1], 8;" :: "r"(d), "l"(s));
}

__global__ void __launch_bounds__(THREADS, 2)
lora_fused_kernel(const float* __restrict__ x,
                  const float* __restrict__ A,
                  const float* __restrict__ B,
                  float* __restrict__ out)
{
    extern __shared__ float sm[];                           // NSTAGES tiles
    __shared__ unsigned long long ts2[ROWS_PER_BLOCK][8];   // t as rank-pairs

    const int tid  = threadIdx.x;
    const int lane = tid & 31;
    const int warp = tid >> 5;
    const int rp   = lane >> 2;       // rank-pair 0..7
    const int ksub = lane & 3;        // k-quarter within 16-k batch
    const long long rowBase  = (long long)blockIdx.x * ROWS_PER_BLOCK;
    const int       warpRow0 = warp * ROWS_PER_WARP;
    const unsigned  smb = su32(sm);

    // ---------------- Phase 1: t[32,16] = x_rows @ A ----------------
    unsigned long long acc[ROWS_PER_WARP];
    #pragma unroll
    for (int r = 0; r < ROWS_PER_WARP; r++) acc[r] = 0ULL;

    // ---- cp.async tile issue: x [32 x 128k] + A rank-pair-major ----
    auto issue = [&](int tile, int stg) {
        const int k0 = tile * KT;
        const unsigned xs = smb + (unsigned)(stg * STAGE_F) * 4u;
        const unsigned as = xs + XS_F * 4u;
        // x: 1024 16B-granules, 8 per thread (32 granules per row)
        #pragma unroll
        for (int m = 0; m < 8; m++) {
            int g   = tid + m * THREADS;
            int row = g >> 5, c = g & 31;
            cpa16(xs + (unsigned)(row * KT + c * 4) * 4u,
                  x + (rowBase + row) * (long long)DIN + k0 + c * 4);
        }
        // A: 1024 8B-granules (128 k x 8 rank-pairs), 8 per thread
        #pragma unroll
        for (int m = 0; m < 8; m++) {
            int g = tid + m * THREADS;
            int k = g >> 3, r8 = g & 7;
            cpa8(as + (unsigned)(r8 * AP + 2 * k) * 4u,
                 A + (long long)(k0 + k) * RNK + 2 * r8);
        }
    };

    #pragma unroll
    for (int s = 0; s < NSTAGES - 1; s++) {
        issue(s, s);
        asm volatile("cp.async.commit_group;");
    }

    #pragma unroll 1
    for (int t = 0; t < NTILES; t++) {
        asm volatile("cp.async.wait_group %0;" :: "n"(NSTAGES - 2));
        __syncthreads();

        const float* xs = sm + (t % NSTAGES) * STAGE_F;
        const float* as = xs + XS_F;
        const float* apbase = as + rp * AP + 8 * ksub;
        const float* xpbase = xs + warpRow0 * KT + 4 * ksub;

        #pragma unroll
        for (int b = 0; b < KT / 16; b++) {
            // A fragment: 8 consecutive floats = ranks(2rp,2rp+1) for 4 k
            const float* ap = apbase + 32 * b;
            ulonglong2 fa = *reinterpret_cast<const ulonglong2*>(ap);
            ulonglong2 fb = *reinterpret_cast<const ulonglong2*>(ap + 4);

            #pragma unroll
            for (int r = 0; r < ROWS_PER_WARP; r++) {
                float4 xv = *reinterpret_cast<const float4*>(
                                xpbase + r * KT + 16 * b);
                ffma2(acc[r], pk2(xv.x), fa.x);
                ffma2(acc[r], pk2(xv.y), fa.y);
                ffma2(acc[r], pk2(xv.z), fb.x);
                ffma2(acc[r], pk2(xv.w), fb.y);
            }
        }

        // refill the stage freed at iteration t-1
        const int nt = t + NSTAGES - 1;
        if (nt < NTILES) issue(nt, nt % NSTAGES);
        asm volatile("cp.async.commit_group;");
    }

    // reduce over the 4 k-quarters within each quad
    #pragma unroll
    for (int r = 0; r < ROWS_PER_WARP; r++) {
        acc[r] = add2(acc[r], __shfl_xor_sync(0xffffffffu, acc[r], 1));
        acc[r] = add2(acc[r], __shfl_xor_sync(0xffffffffu, acc[r], 2));
    }
    if (ksub == 0) {
        #pragma unroll
        for (int r = 0; r < ROWS_PER_WARP; r++)
            ts2[warpRow0 + r][rp] = acc[r];
    }
    __syncthreads();

    // ---------------- Phase 2: out[32,4096] = t @ B ----------------
    // 8 column passes of 512; thread owns 4 columns, B cached in registers,
    // reused across all 32 rows; t read via broadcast LDS.
    #pragma unroll 1
    for (int p = 0; p < 8; p++) {
        const int j = p * 512 + tid * 4;
        ulonglong2 Breg[RNK];
        #pragma unroll
        for (int r = 0; r < RNK; r++)
            Breg[r] = *reinterpret_cast<const ulonglong2*>(B + (long long)r * DOUT + j);

        #pragma unroll 2
        for (int row = 0; row < ROWS_PER_BLOCK; row++) {
            const ulonglong2* tr = reinterpret_cast<const ulonglong2*>(ts2[row]);
            ulonglong2 t0 = tr[0], t1 = tr[1], t2 = tr[2], t3 = tr[3];
            float tv[RNK];
            *reinterpret_cast<ulonglong2*>(&tv[0])  = t0;
            *reinterpret_cast<ulonglong2*>(&tv[4])  = t1;
            *reinterpret_cast<ulonglong2*>(&tv[8])  = t2;
            *reinterpret_cast<ulonglong2*>(&tv[12]) = t3;

            unsigned long long accLo = 0ULL, accHi = 0ULL;
            #pragma unroll
            for (int r = 0; r < RNK; r++) {
                unsigned long long tp = pk2(tv[r]);
                ffma2(accLo, tp, Breg[r].x);
                ffma2(accHi, tp, Breg[r].y);
            }
            ulonglong2 o; o.x = accLo; o.y = accHi;
            *reinterpret_cast<ulonglong2*>(
                out + (rowBase + row) * (long long)DOUT + j) = o;
        }
    }
}

extern "C" void kernel_launch(void* const* d_in, const int* in_sizes, int n_in,
                              void* d_out, int out_size) {
    const float* x = (const float*)d_in[0];   // [4, 2048, 4096]
    const float* A = (const float*)d_in[1];   // [4096, 16]
    const float* B = (const float*)d_in[2];   // [16, 4096]
    float* out = (float*)d_out;               // [4, 2048, 4096]

    cudaFuncSetAttribute(lora_fused_kernel,
                         cudaFuncAttributeMaxDynamicSharedMemorySize, SMEM_BYTES);
    lora_fused_kernel<<<NBLOCKS, THREADS, SMEM_BYTES>>>(x, A, B, out);
}